// round 14
// baseline (speedup 1.0000x reference)
#include <cuda_runtime.h>
#include <cuda_fp16.h>
#include <cstdint>

// ============================================================================
// Problem constants
// ============================================================================
#define M_TOK   8192        // B*S tokens
#define K_DIM   4096        // IN
#define N_DIM   4096        // OUT

#define BM 64
#define BN 128
#define BK 64
#define NK (K_DIM / BK)     // 64 k-tiles
#define STAGES 4
#define THREADS 256         // 8 warps: 2 (M) x 4 (N), warp tile 32x32

#define A_TILE_BYTES (BM * BK)                  // 4096
#define B_TILE_BYTES (BN * BK)                  // 8192
#define STAGE_BYTES  (A_TILE_BYTES + B_TILE_BYTES)   // 12288
#define SMEM_TOTAL   (STAGES * STAGE_BYTES)          // 49152 (3 CTAs/SM)

// ============================================================================
// Device scratch. int8 stored BIASED (+128) and k-PERMUTED within each
// 16-group: stored order = orig k {0,1,8,9, 2,3,10,11, 4,5,12,13, 6,7,14,15}
// so that ldmatrix.x4 on int8 rows delivers bytes in exact m16n8k16
// fragment order (raw m0 -> a0/a2, m1 -> a1/a3; B raw -> b0/b1).
// ============================================================================
__device__ __align__(1024) uint8_t g_xq8[(size_t)M_TOK * K_DIM];  // 32 MB
__device__ __align__(1024) uint8_t g_wb8[(size_t)N_DIM * K_DIM];  // 16 MB
__device__ float g_alpha[M_TOK];

// ============================================================================
// PTX helpers
// ============================================================================
__device__ __forceinline__ uint32_t smem_to_u32(const void* p) {
    uint32_t a;
    asm("{ .reg .u64 t; cvta.to.shared.u64 t, %1; cvt.u32.u64 %0, t; }"
        : "=r"(a) : "l"(p));
    return a;
}

__device__ __forceinline__ void cp_async16(uint32_t smem_addr, const void* gptr) {
    asm volatile("cp.async.cg.shared.global [%0], [%1], 16;"
                 :: "r"(smem_addr), "l"(gptr) : "memory");
}
__device__ __forceinline__ void cp_commit() {
    asm volatile("cp.async.commit_group;" ::: "memory");
}
template <int N>
__device__ __forceinline__ void cp_wait() {
    asm volatile("cp.async.wait_group %0;" :: "n"(N) : "memory");
}

__device__ __forceinline__ void ldsm_x4(uint32_t addr, uint32_t* r) {
    asm volatile("ldmatrix.sync.aligned.m8n8.x4.shared.b16 {%0,%1,%2,%3}, [%4];"
                 : "=r"(r[0]), "=r"(r[1]), "=r"(r[2]), "=r"(r[3]) : "r"(addr));
}

// Dequant: raw u32 of 4 biased bytes [u0,u1,u2,u3] (= orig k {2q,2q+1,2q+8,
// 2q+9} + 128) -> two fp16x2 regs holding (k2q,k2q+1) and (k2q+8,k2q+9).
// fp16 trick: prmt byte into mantissa of 1024-biased fp16, subtract 1152.
__device__ __forceinline__ void cvt_pair(uint32_t raw, uint32_t& lo, uint32_t& hi) {
    uint32_t t0, t1;
    asm("prmt.b32 %0, %1, %2, 0x4140;" : "=r"(t0) : "r"(raw), "r"(0x64646464u));
    asm("prmt.b32 %0, %1, %2, 0x4342;" : "=r"(t1) : "r"(raw), "r"(0x64646464u));
    asm("sub.f16x2 %0, %1, %2;" : "=r"(lo) : "r"(t0), "r"(0x64806480u));
    asm("sub.f16x2 %0, %1, %2;" : "=r"(hi) : "r"(t1), "r"(0x64806480u));
}

// m16n8k16 fp16 inputs, fp32 accumulate
__device__ __forceinline__ void mma_f16(float* c, uint32_t a0, uint32_t a1,
                                        uint32_t a2, uint32_t a3,
                                        uint32_t b0, uint32_t b1) {
    asm volatile(
        "mma.sync.aligned.m16n8k16.row.col.f32.f16.f16.f32 "
        "{%0,%1,%2,%3}, {%4,%5,%6,%7}, {%8,%9}, {%0,%1,%2,%3};"
        : "+f"(c[0]), "+f"(c[1]), "+f"(c[2]), "+f"(c[3])
        : "r"(a0), "r"(a1), "r"(a2), "r"(a3), "r"(b0), "r"(b1));
}

__device__ __forceinline__ uint32_t pack4(float a, float b, float c, float d,
                                          float inv) {
    int q0 = (int)fminf(fmaxf(rintf(a * inv), -127.0f), 127.0f) + 128;
    int q1 = (int)fminf(fmaxf(rintf(b * inv), -127.0f), 127.0f) + 128;
    int q2 = (int)fminf(fmaxf(rintf(c * inv), -127.0f), 127.0f) + 128;
    int q3 = (int)fminf(fmaxf(rintf(d * inv), -127.0f), 127.0f) + 128;
    return (uint32_t)q0 | ((uint32_t)q1 << 8) | ((uint32_t)q2 << 16) |
           ((uint32_t)q3 << 24);
}

// ============================================================================
// Kernel 1: per-token absmax quantize x -> biased+permuted int8,
// alpha = gamma/127*scale.  Thread handles 2 16-groups.
// ============================================================================
__global__ void __launch_bounds__(128)
quant_kernel(const float* __restrict__ x, const float* __restrict__ scale_p,
             uint8_t* __restrict__ xq8, float* __restrict__ alpha)
{
    const int token = blockIdx.x;
    const int tid = threadIdx.x;
    const float4* xr = reinterpret_cast<const float4*>(x + (size_t)token * K_DIM);

    float4 v[8];                       // 2 groups x 4 float4
    float m = 0.0f;
#pragma unroll
    for (int i = 0; i < 2; i++)
#pragma unroll
        for (int j = 0; j < 4; j++) {
            float4 t = xr[(tid + i * 128) * 4 + j];
            v[i * 4 + j] = t;
            m = fmaxf(m, fmaxf(fmaxf(fabsf(t.x), fabsf(t.y)),
                               fmaxf(fabsf(t.z), fabsf(t.w))));
        }
#pragma unroll
    for (int o = 16; o; o >>= 1) m = fmaxf(m, __shfl_xor_sync(0xFFFFFFFFu, m, o));

    __shared__ float wmax[4];
    __shared__ float s_inv;
    if ((tid & 31) == 0) wmax[tid >> 5] = m;
    __syncthreads();
    if (tid == 0) {
        float g = fmaxf(fmaxf(wmax[0], wmax[1]), fmaxf(wmax[2], wmax[3]));
        g = fmaxf(g, 1e-5f);
        s_inv = 127.0f / g;
        alpha[token] = g * (1.0f / 127.0f) * scale_p[0];
    }
    __syncthreads();
    const float inv = s_inv;

    uint4* xo = reinterpret_cast<uint4*>(xq8 + (size_t)token * K_DIM);
#pragma unroll
    for (int i = 0; i < 2; i++) {
        float4 v0 = v[i * 4 + 0], v1 = v[i * 4 + 1];
        float4 v2 = v[i * 4 + 2], v3 = v[i * 4 + 3];
        uint4 o;
        o.x = pack4(v0.x, v0.y, v2.x, v2.y, inv);   // k {0,1,8,9}
        o.y = pack4(v0.z, v0.w, v2.z, v2.w, inv);   // k {2,3,10,11}
        o.z = pack4(v1.x, v1.y, v3.x, v3.y, inv);   // k {4,5,12,13}
        o.w = pack4(v1.z, v1.w, v3.z, v3.w, inv);   // k {6,7,14,15}
        xo[tid + i * 128] = o;
    }
}

// ============================================================================
// Kernel 2: w (float {-1,0,1}) -> biased+permuted int8. One 16-group/thread.
// ============================================================================
__global__ void __launch_bounds__(256)
wconv_kernel(const float* __restrict__ w, uint8_t* __restrict__ wb8)
{
    size_t gidx = (size_t)blockIdx.x * blockDim.x + threadIdx.x;  // 16-group
    const float4* wr = reinterpret_cast<const float4*>(w) + gidx * 4;
    float4 v0 = wr[0], v1 = wr[1], v2 = wr[2], v3 = wr[3];
    uint4 o;
    o.x = pack4(v0.x, v0.y, v2.x, v2.y, 1.0f);
    o.y = pack4(v0.z, v0.w, v2.z, v2.w, 1.0f);
    o.z = pack4(v1.x, v1.y, v3.x, v3.y, 1.0f);
    o.w = pack4(v1.z, v1.w, v3.z, v3.w, 1.0f);
    reinterpret_cast<uint4*>(wb8)[gidx] = o;
}

// ============================================================================
// Kernel 3: int8-fed fp16 HMMA GEMM. BM=64 x BN=128 x BK=64, 4-stage cp.async,
// 3 CTAs/SM (independent barrier domains, 6 warps/SMSP).
// 8 warps: 2 (M) x 4 (N), warp tile 32x32.
// int8 tiles in smem (64 B rows, swizzle (c16*16)^((row&6)<<3)); dequant to
// fp16 fragments in registers via prmt/sub.f16x2 (exact).
// Per warp per k-tile: 8 ldsm.x4 + 128 cvt ops + 32 HMMA.
// ============================================================================
__global__ void __launch_bounds__(THREADS, 3)
bitlinear_gemm(const uint8_t* __restrict__ xq8, const uint8_t* __restrict__ wb8,
               const float* __restrict__ alpha, float* __restrict__ out)
{
    extern __shared__ int8_t smem[];
    const uint32_t su = smem_to_u32(smem);

    const int tid  = threadIdx.x;
    const int lane = tid & 31;
    const int wid  = tid >> 5;
    const int wm   = wid >> 2;            // 0..1 (M dim)
    const int wn   = wid & 3;             // 0..3 (N dim)

    const int m0 = blockIdx.y * BM;
    const int n0 = blockIdx.x * BN;

    // --- cp.async: A 1 chunk, B 2 chunks per thread per stage ---
    {
    }
    const int a_row = tid >> 2, a_c16 = tid & 3;
    const int dstA = a_row * 64 + ((a_c16 * 16) ^ ((a_row & 6) << 3));
    const uint8_t* gA = xq8 + (size_t)(m0 + a_row) * K_DIM + a_c16 * 16;
    int dstB[2];
    const uint8_t* gB[2];
#pragma unroll
    for (int i = 0; i < 2; i++) {
        int c = tid + i * THREADS;         // 0..511
        int row = c >> 2, c16 = c & 3;
        dstB[i] = A_TILE_BYTES + row * 64 + ((c16 * 16) ^ ((row & 6) << 3));
        gB[i] = wb8 + (size_t)(n0 + row) * K_DIM + c16 * 16;
    }

    // --- ldmatrix base offsets: 16 rows x 2 kgroups per x4.
    // lane -> row += (lane&15), kgroup = lane>>4. Pair p: addr = base^(p<<5).
    const int lrow = lane & 15;
    const int kg0  = (lane >> 4) * 16;
    int baseA[2], baseB[2];
#pragma unroll
    for (int f = 0; f < 2; f++) {
        int row = wm * 32 + f * 16 + lrow;
        baseA[f] = row * 64 + (kg0 ^ ((row & 6) << 3));
    }
#pragma unroll
    for (int j = 0; j < 2; j++) {
        int row = wn * 32 + j * 16 + lrow;
        baseB[j] = A_TILE_BYTES + row * 64 + (kg0 ^ ((row & 6) << 3));
    }

    float acc[2][4][4];                    // 32 regs
#pragma unroll
    for (int f = 0; f < 2; f++)
#pragma unroll
        for (int j = 0; j < 4; j++)
#pragma unroll
            for (int c = 0; c < 4; c++) acc[f][j][c] = 0.0f;

    // --- prologue: issue STAGES-1 stages ---
#pragma unroll
    for (int s = 0; s < STAGES - 1; s++) {
        const uint32_t sb = su + s * STAGE_BYTES;
        cp_async16(sb + dstA, gA + s * BK);
#pragma unroll
        for (int i = 0; i < 2; i++)
            cp_async16(sb + dstB[i], gB[i] + s * BK);
        cp_commit();
    }

    // --- mainloop ---
    int cur = 0, nxt = STAGES - 1;
    for (int kt = 0; kt < NK; kt++) {
        cp_wait<STAGES - 2>();
        __syncthreads();

        int jt = kt + STAGES - 1;
        if (jt < NK) {
            const uint32_t sb = su + nxt * STAGE_BYTES;
            cp_async16(sb + dstA, gA + jt * BK);
#pragma unroll
            for (int i = 0; i < 2; i++)
                cp_async16(sb + dstB[i], gB[i] + jt * BK);
        }
        cp_commit();

        const uint32_t st = su + cur * STAGE_BYTES;

#pragma unroll
        for (int p = 0; p < 2; p++) {          // kstep pairs
            const int px = p << 5;
            uint32_t rawA[2][4], rawB[2][4];
#pragma unroll
            for (int f = 0; f < 2; f++) ldsm_x4(st + (baseA[f] ^ px), rawA[f]);
#pragma unroll
            for (int j = 0; j < 2; j++) ldsm_x4(st + (baseB[j] ^ px), rawB[j]);

#pragma unroll
            for (int ks = 0; ks < 2; ks++) {   // ksteps within pair
                uint32_t a[2][4], b2[4][2];
#pragma unroll
                for (int f = 0; f < 2; f++) {
                    cvt_pair(rawA[f][2 * ks],     a[f][0], a[f][2]);
                    cvt_pair(rawA[f][2 * ks + 1], a[f][1], a[f][3]);
                }
#pragma unroll
                for (int j = 0; j < 2; j++) {
                    cvt_pair(rawB[j][2 * ks],     b2[2 * j][0],     b2[2 * j][1]);
                    cvt_pair(rawB[j][2 * ks + 1], b2[2 * j + 1][0], b2[2 * j + 1][1]);
                }
#pragma unroll
                for (int f = 0; f < 2; f++)
#pragma unroll
                    for (int j8 = 0; j8 < 4; j8++)
                        mma_f16(acc[f][j8],
                                a[f][0], a[f][1], a[f][2], a[f][3],
                                b2[j8][0], b2[j8][1]);
            }
        }

        cur = (cur == STAGES - 1) ? 0 : cur + 1;
        nxt = (nxt == STAGES - 1) ? 0 : nxt + 1;
    }

    // --- epilogue: dequantize + store ---
#pragma unroll
    for (int f = 0; f < 2; f++) {
        int r0 = m0 + wm * 32 + f * 16 + (lane >> 2);
        float al0 = alpha[r0];
        float al1 = alpha[r0 + 8];
        float* o0 = out + (size_t)r0 * N_DIM + n0 + wn * 32 + (lane & 3) * 2;
        float* o1 = o0 + (size_t)8 * N_DIM;
#pragma unroll
        for (int j = 0; j < 4; j++) {
            float2 v0, v1;
            v0.x = acc[f][j][0] * al0;
            v0.y = acc[f][j][1] * al0;
            v1.x = acc[f][j][2] * al1;
            v1.y = acc[f][j][3] * al1;
            *reinterpret_cast<float2*>(o0 + j * 8) = v0;
            *reinterpret_cast<float2*>(o1 + j * 8) = v1;
        }
    }
}

// ============================================================================
// Host side
// ============================================================================
extern "C" void kernel_launch(void* const* d_in, const int* in_sizes, int n_in,
                              void* d_out, int out_size)
{
    const float* x     = (const float*)d_in[0];
    const float* w     = (const float*)d_in[1];
    const float* scale = (const float*)d_in[2];
    float* out = (float*)d_out;

    void *xq8_p = nullptr, *wb8_p = nullptr, *al_p = nullptr;
    cudaGetSymbolAddress(&xq8_p, g_xq8);
    cudaGetSymbolAddress(&wb8_p, g_wb8);
    cudaGetSymbolAddress(&al_p, g_alpha);

    // Phase 1: quantize activations + convert weights (biased+permuted int8)
    quant_kernel<<<M_TOK, 128>>>(x, scale, (uint8_t*)xq8_p, (float*)al_p);
    wconv_kernel<<<((size_t)N_DIM * K_DIM / 16) / 256, 256>>>(
        w, (uint8_t*)wb8_p);

    // Phase 2: GEMM (3 CTAs per SM, int8-fed fp16 HMMA)
    cudaFuncSetAttribute(bitlinear_gemm,
                         cudaFuncAttributeMaxDynamicSharedMemorySize, SMEM_TOTAL);
    dim3 grid(N_DIM / BN, M_TOK / BM);   // 32 x 128 = 4096 CTAs
    bitlinear_gemm<<<grid, THREADS, SMEM_TOTAL>>>(
        (const uint8_t*)xq8_p, (const uint8_t*)wb8_p, (const float*)al_p, out);
}

// round 15
// speedup vs baseline: 1.0875x; 1.0875x over previous
#include <cuda_runtime.h>
#include <cuda_fp16.h>
#include <cstdint>

// ============================================================================
// Problem constants
// ============================================================================
#define M_TOK   8192        // B*S tokens
#define K_DIM   4096        // IN
#define N_DIM   4096        // OUT

#define BM 128
#define BN 128
#define BK 64
#define NK (K_DIM / BK)     // 64 k-tiles
#define STAGES 3
#define THREADS 256         // 8 warps: 4 (M) x 2 (N), warp tile 32x64

#define TILE_ROW_BYTES 128                       // 64 fp16
#define A_TILE_BYTES (BM * TILE_ROW_BYTES)       // 16384
#define B_TILE_BYTES (BN * TILE_ROW_BYTES)       // 16384
#define STAGE_BYTES  (A_TILE_BYTES + B_TILE_BYTES)   // 32768
#define SMEM_TOTAL   (STAGES * STAGE_BYTES)          // 98304 (2 CTAs/SM)

// ============================================================================
// Device scratch (no dynamic allocation allowed)
// ============================================================================
__device__ __align__(1024) __half g_xq[(size_t)M_TOK * K_DIM];   // 64 MB
__device__ __align__(1024) __half g_wb[(size_t)N_DIM * K_DIM];   // 32 MB
__device__ float g_alpha[M_TOK];

// ============================================================================
// PTX helpers
// ============================================================================
__device__ __forceinline__ uint32_t smem_to_u32(const void* p) {
    uint32_t a;
    asm("{ .reg .u64 t; cvta.to.shared.u64 t, %1; cvt.u32.u64 %0, t; }"
        : "=r"(a) : "l"(p));
    return a;
}

__device__ __forceinline__ void cp_async16(uint32_t smem_addr, const void* gptr) {
    asm volatile("cp.async.cg.shared.global [%0], [%1], 16;"
                 :: "r"(smem_addr), "l"(gptr) : "memory");
}
__device__ __forceinline__ void cp_commit() {
    asm volatile("cp.async.commit_group;" ::: "memory");
}
template <int N>
__device__ __forceinline__ void cp_wait() {
    asm volatile("cp.async.wait_group %0;" :: "n"(N) : "memory");
}

__device__ __forceinline__ void ldsm_x4(uint32_t addr, uint32_t* r) {
    asm volatile("ldmatrix.sync.aligned.m8n8.x4.shared.b16 {%0,%1,%2,%3}, [%4];"
                 : "=r"(r[0]), "=r"(r[1]), "=r"(r[2]), "=r"(r[3]) : "r"(addr));
}

// Streaming store (evict-first): keeps the write-once output stream from
// evicting the L2-resident B tiles.
__device__ __forceinline__ void stg_cs_v2(float* p, float a, float b) {
    asm volatile("st.global.cs.v2.f32 [%0], {%1, %2};"
                 :: "l"(p), "f"(a), "f"(b) : "memory");
}

// m16n8k16 fp16 inputs, fp32 accumulate
__device__ __forceinline__ void mma_f16(float* c, uint32_t a0, uint32_t a1,
                                        uint32_t a2, uint32_t a3,
                                        uint32_t b0, uint32_t b1) {
    asm volatile(
        "mma.sync.aligned.m16n8k16.row.col.f32.f16.f16.f32 "
        "{%0,%1,%2,%3}, {%4,%5,%6,%7}, {%8,%9}, {%0,%1,%2,%3};"
        : "+f"(c[0]), "+f"(c[1]), "+f"(c[2]), "+f"(c[3])
        : "r"(a0), "r"(a1), "r"(a2), "r"(a3), "r"(b0), "r"(b1));
}

// ============================================================================
// Kernel 1: per-token absmax quantize x -> fp16 (exact small ints),
// alpha = gamma/127*scale
// ============================================================================
__global__ void __launch_bounds__(128)
quant_kernel(const float* __restrict__ x, const float* __restrict__ scale_p,
             __half* __restrict__ xq, float* __restrict__ alpha)
{
    const int token = blockIdx.x;
    const int tid = threadIdx.x;
    const float4* xr = reinterpret_cast<const float4*>(x + (size_t)token * K_DIM);

    float4 v[8];
    float m = 0.0f;
#pragma unroll
    for (int i = 0; i < 8; i++) {
        v[i] = xr[tid + i * 128];
        m = fmaxf(m, fmaxf(fmaxf(fabsf(v[i].x), fabsf(v[i].y)),
                           fmaxf(fabsf(v[i].z), fabsf(v[i].w))));
    }
#pragma unroll
    for (int o = 16; o; o >>= 1) m = fmaxf(m, __shfl_xor_sync(0xFFFFFFFFu, m, o));

    __shared__ float wmax[4];
    __shared__ float s_inv;
    if ((tid & 31) == 0) wmax[tid >> 5] = m;
    __syncthreads();
    if (tid == 0) {
        float g = fmaxf(fmaxf(wmax[0], wmax[1]), fmaxf(wmax[2], wmax[3]));
        g = fmaxf(g, 1e-5f);
        s_inv = 127.0f / g;
        alpha[token] = g * (1.0f / 127.0f) * scale_p[0];
    }
    __syncthreads();
    const float inv = s_inv;

    __half2* xqr = reinterpret_cast<__half2*>(xq + (size_t)token * K_DIM);
#pragma unroll
    for (int i = 0; i < 8; i++) {
        float q0 = fminf(fmaxf(rintf(v[i].x * inv), -127.0f), 127.0f);
        float q1 = fminf(fmaxf(rintf(v[i].y * inv), -127.0f), 127.0f);
        float q2 = fminf(fmaxf(rintf(v[i].z * inv), -127.0f), 127.0f);
        float q3 = fminf(fmaxf(rintf(v[i].w * inv), -127.0f), 127.0f);
        __half2 p0, p1;
        p0.x = __float2half_rn(q0); p0.y = __float2half_rn(q1);
        p1.x = __float2half_rn(q2); p1.y = __float2half_rn(q3);
        int base = (tid + i * 128) * 2;
        xqr[base]     = p0;
        xqr[base + 1] = p1;
    }
}

// ============================================================================
// Kernel 2: w (float, values in {-1,0,1}) -> fp16
// ============================================================================
__global__ void __launch_bounds__(256)
wconv_kernel(const float* __restrict__ w, __half* __restrict__ wb)
{
    size_t idx = (size_t)blockIdx.x * blockDim.x + threadIdx.x;  // float4 index
    float4 v = reinterpret_cast<const float4*>(w)[idx];
    __half2 p0, p1;
    p0.x = __float2half_rn(v.x); p0.y = __float2half_rn(v.y);
    p1.x = __float2half_rn(v.z); p1.y = __float2half_rn(v.w);
    reinterpret_cast<__half2*>(wb)[idx * 2]     = p0;
    reinterpret_cast<__half2*>(wb)[idx * 2 + 1] = p1;
}

// ============================================================================
// Kernel 3: fp16 HMMA GEMM, BM=128 x BN=128 x BK=64, 3-stage cp.async pipeline,
// 2 CTAs per SM. 8 warps: 4 (M) x 2 (N); warp tile 32x64.
// (R7 champion config + streaming epilogue stores + hoisted alpha loads.)
// SMEM rows 128 B. Swizzle: o ^ (((o>>7)&7)<<4);
// k-step fragment addr: off[s] = off_base ^ (s<<5).
// ============================================================================
__global__ void __launch_bounds__(THREADS, 2)
bitlinear_gemm(const __half* __restrict__ xq, const __half* __restrict__ wb,
               const float* __restrict__ alpha, float* __restrict__ out)
{
    extern __shared__ int8_t smem[];
    const uint32_t smem_u = smem_to_u32(smem);

    const int tid  = threadIdx.x;
    const int lane = tid & 31;
    const int wid  = tid >> 5;
    const int wm   = wid >> 1;            // 0..3 (M dim)
    const int wn   = wid & 1;             // 0..1 (N dim)

    const int m0 = blockIdx.y * BM;
    const int n0 = blockIdx.x * BN;

    // hoist alpha loads off the epilogue critical path
    float al[2][2];
#pragma unroll
    for (int f = 0; f < 2; f++) {
        int r0 = m0 + wm * 32 + f * 16 + (lane >> 2);
        al[f][0] = alpha[r0];
        al[f][1] = alpha[r0 + 8];
    }

    // --- cp.async: A 4 chunks, B 4 chunks per thread per stage ---
    const int ld_row = tid >> 3;           // 0..31
    const int ld_col = tid & 7;
    const int dstA0 = ld_row * TILE_ROW_BYTES +
                      ((ld_col * 16) ^ ((ld_row & 7) << 4));
    const int dstB0 = A_TILE_BYTES + dstA0;
    const int8_t* gA0 = reinterpret_cast<const int8_t*>(xq) +
                        ((size_t)(m0 + ld_row) * K_DIM) * 2 + ld_col * 16;
    const int8_t* gB0 = reinterpret_cast<const int8_t*>(wb) +
                        ((size_t)(n0 + ld_row) * K_DIM) * 2 + ld_col * 16;
    const size_t GSTEP = (size_t)32 * K_DIM * 2;   // 32 rows in gmem bytes

    // --- ldmatrix base offsets (k-step 0); off[s] = base ^ (s<<5) ---
    const int g  = lane >> 3;
    const int lr = lane & 7;
    int offA[2], offB[4];
#pragma unroll
    for (int f = 0; f < 2; f++) {
        int row = wm * 32 + f * 16 + (g & 1) * 8 + lr;
        int kb  = (g >> 1) * 16;
        offA[f] = row * TILE_ROW_BYTES + (kb ^ ((row & 7) << 4));
    }
#pragma unroll
    for (int j2 = 0; j2 < 4; j2++) {
        int row = wn * 64 + j2 * 16 + (g & 1) * 8 + lr;
        int kb  = (g >> 1) * 16;
        offB[j2] = A_TILE_BYTES + row * TILE_ROW_BYTES + (kb ^ ((row & 7) << 4));
    }

    float acc[2][8][4];                   // [m-frag][n8-frag][4] = 64 regs
#pragma unroll
    for (int f = 0; f < 2; f++)
#pragma unroll
        for (int j = 0; j < 8; j++)
#pragma unroll
            for (int c = 0; c < 4; c++) acc[f][j][c] = 0.0f;

    // --- prologue: issue STAGES-1 stages ---
#pragma unroll
    for (int s = 0; s < STAGES - 1; s++) {
        const uint32_t sb = smem_u + s * STAGE_BYTES;
#pragma unroll
        for (int i = 0; i < 4; i++)
            cp_async16(sb + dstA0 + i * 4096, gA0 + i * GSTEP + s * (BK * 2));
#pragma unroll
        for (int i = 0; i < 4; i++)
            cp_async16(sb + dstB0 + i * 4096, gB0 + i * GSTEP + s * (BK * 2));
        cp_commit();
    }

    // --- mainloop ---
    int cur = 0;
    int nxt = STAGES - 1;
    for (int kt = 0; kt < NK; kt++) {
        cp_wait<STAGES - 2>();
        __syncthreads();

        int jt = kt + STAGES - 1;
        if (jt < NK) {
            const uint32_t sb = smem_u + nxt * STAGE_BYTES;
#pragma unroll
            for (int i = 0; i < 4; i++)
                cp_async16(sb + dstA0 + i * 4096, gA0 + i * GSTEP + jt * (BK * 2));
#pragma unroll
            for (int i = 0; i < 4; i++)
                cp_async16(sb + dstB0 + i * 4096, gB0 + i * GSTEP + jt * (BK * 2));
        }
        cp_commit();

        const uint32_t st = smem_u + cur * STAGE_BYTES;

#pragma unroll
        for (int s = 0; s < 4; s++) {
            const int sx = s << 5;
            uint32_t af[2][4], bf[4][4];
#pragma unroll
            for (int f = 0; f < 2; f++)    ldsm_x4(st + (offA[f] ^ sx), af[f]);
#pragma unroll
            for (int j2 = 0; j2 < 4; j2++) ldsm_x4(st + (offB[j2] ^ sx), bf[j2]);
            // bf[j2] regs: {n0-7 k0-7, n8-15 k0-7, n0-7 k8-15, n8-15 k8-15}
#pragma unroll
            for (int f = 0; f < 2; f++)
#pragma unroll
                for (int j = 0; j < 8; j++)
                    mma_f16(acc[f][j],
                            af[f][0], af[f][1], af[f][2], af[f][3],
                            bf[j >> 1][(j & 1)], bf[j >> 1][(j & 1) + 2]);
        }

        cur = (cur == STAGES - 1) ? 0 : cur + 1;
        nxt = (nxt == STAGES - 1) ? 0 : nxt + 1;
    }

    // --- epilogue: dequantize + streaming store ---
#pragma unroll
    for (int f = 0; f < 2; f++) {
        int r0 = m0 + wm * 32 + f * 16 + (lane >> 2);
        float al0 = al[f][0];
        float al1 = al[f][1];
        float* o0 = out + (size_t)r0 * N_DIM + n0 + wn * 64 + (lane & 3) * 2;
        float* o1 = o0 + (size_t)8 * N_DIM;
#pragma unroll
        for (int j = 0; j < 8; j++) {
            stg_cs_v2(o0 + j * 8, acc[f][j][0] * al0, acc[f][j][1] * al0);
            stg_cs_v2(o1 + j * 8, acc[f][j][2] * al1, acc[f][j][3] * al1);
        }
    }
}

// ============================================================================
// Host side
// ============================================================================
extern "C" void kernel_launch(void* const* d_in, const int* in_sizes, int n_in,
                              void* d_out, int out_size)
{
    const float* x     = (const float*)d_in[0];
    const float* w     = (const float*)d_in[1];
    const float* scale = (const float*)d_in[2];
    float* out = (float*)d_out;

    void *xq_p = nullptr, *wb_p = nullptr, *al_p = nullptr;
    cudaGetSymbolAddress(&xq_p, g_xq);
    cudaGetSymbolAddress(&wb_p, g_wb);
    cudaGetSymbolAddress(&al_p, g_alpha);

    // Phase 1: quantize activations + convert weights
    quant_kernel<<<M_TOK, 128>>>(x, scale, (__half*)xq_p, (float*)al_p);
    wconv_kernel<<<((size_t)N_DIM * K_DIM) / (256 * 4), 256>>>(w, (__half*)wb_p);

    // Phase 2: GEMM (2 CTAs per SM)
    cudaFuncSetAttribute(bitlinear_gemm,
                         cudaFuncAttributeMaxDynamicSharedMemorySize, SMEM_TOTAL);
    dim3 grid(N_DIM / BN, M_TOK / BM);   // 32 x 64 = 2048 CTAs
    bitlinear_gemm<<<grid, THREADS, SMEM_TOTAL>>>(
        (const __half*)xq_p, (const __half*)wb_p, (const float*)al_p, out);
}

// round 16
// speedup vs baseline: 1.1465x; 1.0543x over previous
#include <cuda_runtime.h>
#include <cuda_fp16.h>
#include <cstdint>

// ============================================================================
// Problem constants
// ============================================================================
#define M_TOK   8192        // B*S tokens
#define K_DIM   4096        // IN
#define N_DIM   4096        // OUT

#define BM 128
#define BN 128
#define BK 64
#define NK (K_DIM / BK)     // 64 k-tiles
#define STAGES 3
#define THREADS 256         // 8 warps: 4 (M) x 2 (N), warp tile 32x64

#define TILE_ROW_BYTES 128                       // 64 fp16
#define A_TILE_BYTES (BM * TILE_ROW_BYTES)       // 16384
#define B_TILE_BYTES (BN * TILE_ROW_BYTES)       // 16384
#define STAGE_BYTES  (A_TILE_BYTES + B_TILE_BYTES)   // 32768
#define SMEM_TOTAL   (STAGES * STAGE_BYTES)          // 98304 (2 CTAs/SM)

// ============================================================================
// Device scratch (no dynamic allocation allowed)
// ============================================================================
__device__ __align__(1024) __half g_xq[(size_t)M_TOK * K_DIM];   // 64 MB
__device__ __align__(1024) __half g_wb[(size_t)N_DIM * K_DIM];   // 32 MB
__device__ float g_alpha[M_TOK];

// ============================================================================
// PTX helpers
// ============================================================================
__device__ __forceinline__ uint32_t smem_to_u32(const void* p) {
    uint32_t a;
    asm("{ .reg .u64 t; cvta.to.shared.u64 t, %1; cvt.u32.u64 %0, t; }"
        : "=r"(a) : "l"(p));
    return a;
}

__device__ __forceinline__ void cp_async16(uint32_t smem_addr, const void* gptr) {
    asm volatile("cp.async.cg.shared.global [%0], [%1], 16;"
                 :: "r"(smem_addr), "l"(gptr) : "memory");
}
__device__ __forceinline__ void cp_commit() {
    asm volatile("cp.async.commit_group;" ::: "memory");
}
template <int N>
__device__ __forceinline__ void cp_wait() {
    asm volatile("cp.async.wait_group %0;" :: "n"(N) : "memory");
}

__device__ __forceinline__ void ldsm_x4(uint32_t addr, uint32_t* r) {
    asm volatile("ldmatrix.sync.aligned.m8n8.x4.shared.b16 {%0,%1,%2,%3}, [%4];"
                 : "=r"(r[0]), "=r"(r[1]), "=r"(r[2]), "=r"(r[3]) : "r"(addr));
}

// m16n8k16 fp16 inputs, fp32 accumulate
__device__ __forceinline__ void mma_f16(float* c, uint32_t a0, uint32_t a1,
                                        uint32_t a2, uint32_t a3,
                                        uint32_t b0, uint32_t b1) {
    asm volatile(
        "mma.sync.aligned.m16n8k16.row.col.f32.f16.f16.f32 "
        "{%0,%1,%2,%3}, {%4,%5,%6,%7}, {%8,%9}, {%0,%1,%2,%3};"
        : "+f"(c[0]), "+f"(c[1]), "+f"(c[2]), "+f"(c[3])
        : "r"(a0), "r"(a1), "r"(a2), "r"(a3), "r"(b0), "r"(b1));
}

// ============================================================================
// Kernel 1: per-token absmax quantize x -> fp16 (exact small ints),
// alpha = gamma/127*scale
// ============================================================================
__global__ void __launch_bounds__(128)
quant_kernel(const float* __restrict__ x, const float* __restrict__ scale_p,
             __half* __restrict__ xq, float* __restrict__ alpha)
{
    const int token = blockIdx.x;
    const int tid = threadIdx.x;
    const float4* xr = reinterpret_cast<const float4*>(x + (size_t)token * K_DIM);

    float4 v[8];
    float m = 0.0f;
#pragma unroll
    for (int i = 0; i < 8; i++) {
        v[i] = xr[tid + i * 128];
        m = fmaxf(m, fmaxf(fmaxf(fabsf(v[i].x), fabsf(v[i].y)),
                           fmaxf(fabsf(v[i].z), fabsf(v[i].w))));
    }
#pragma unroll
    for (int o = 16; o; o >>= 1) m = fmaxf(m, __shfl_xor_sync(0xFFFFFFFFu, m, o));

    __shared__ float wmax[4];
    __shared__ float s_inv;
    if ((tid & 31) == 0) wmax[tid >> 5] = m;
    __syncthreads();
    if (tid == 0) {
        float g = fmaxf(fmaxf(wmax[0], wmax[1]), fmaxf(wmax[2], wmax[3]));
        g = fmaxf(g, 1e-5f);
        s_inv = 127.0f / g;
        alpha[token] = g * (1.0f / 127.0f) * scale_p[0];
    }
    __syncthreads();
    const float inv = s_inv;

    __half2* xqr = reinterpret_cast<__half2*>(xq + (size_t)token * K_DIM);
#pragma unroll
    for (int i = 0; i < 8; i++) {
        float q0 = fminf(fmaxf(rintf(v[i].x * inv), -127.0f), 127.0f);
        float q1 = fminf(fmaxf(rintf(v[i].y * inv), -127.0f), 127.0f);
        float q2 = fminf(fmaxf(rintf(v[i].z * inv), -127.0f), 127.0f);
        float q3 = fminf(fmaxf(rintf(v[i].w * inv), -127.0f), 127.0f);
        __half2 p0, p1;
        p0.x = __float2half_rn(q0); p0.y = __float2half_rn(q1);
        p1.x = __float2half_rn(q2); p1.y = __float2half_rn(q3);
        int base = (tid + i * 128) * 2;
        xqr[base]     = p0;
        xqr[base + 1] = p1;
    }
}

// ============================================================================
// Kernel 2: w (float, values in {-1,0,1}) -> fp16
// ============================================================================
__global__ void __launch_bounds__(256)
wconv_kernel(const float* __restrict__ w, __half* __restrict__ wb)
{
    size_t idx = (size_t)blockIdx.x * blockDim.x + threadIdx.x;  // float4 index
    float4 v = reinterpret_cast<const float4*>(w)[idx];
    __half2 p0, p1;
    p0.x = __float2half_rn(v.x); p0.y = __float2half_rn(v.y);
    p1.x = __float2half_rn(v.z); p1.y = __float2half_rn(v.w);
    reinterpret_cast<__half2*>(wb)[idx * 2]     = p0;
    reinterpret_cast<__half2*>(wb)[idx * 2 + 1] = p1;
}

// ============================================================================
// Kernel 3: fp16 HMMA GEMM, BM=128 x BN=128 x BK=64, 3-stage cp.async pipeline,
// 2 CTAs per SM. 8 warps: 4 (M) x 2 (N); warp tile 32x64.
// R7 champion config with DEFERRED PREFETCH: the cp.async burst for tile
// kt+2 is issued between ksteps (after kstep0's ldsm+MMA has fed the tensor
// pipe) instead of immediately after the barrier, so the post-barrier LSU
// burst no longer delays kstep0's ldmatrix and starves the tensor pipe.
// SMEM rows 128 B. Swizzle: o ^ (((o>>7)&7)<<4);
// k-step fragment addr: off[s] = off_base ^ (s<<5).
// ============================================================================
__global__ void __launch_bounds__(THREADS, 2)
bitlinear_gemm(const __half* __restrict__ xq, const __half* __restrict__ wb,
               const float* __restrict__ alpha, float* __restrict__ out)
{
    extern __shared__ int8_t smem[];
    const uint32_t smem_u = smem_to_u32(smem);

    const int tid  = threadIdx.x;
    const int lane = tid & 31;
    const int wid  = tid >> 5;
    const int wm   = wid >> 1;            // 0..3 (M dim)
    const int wn   = wid & 1;             // 0..1 (N dim)

    const int m0 = blockIdx.y * BM;
    const int n0 = blockIdx.x * BN;

    // --- cp.async: A 4 chunks, B 4 chunks per thread per stage ---
    const int ld_row = tid >> 3;           // 0..31
    const int ld_col = tid & 7;
    const int dstA0 = ld_row * TILE_ROW_BYTES +
                      ((ld_col * 16) ^ ((ld_row & 7) << 4));
    const int dstB0 = A_TILE_BYTES + dstA0;
    const int8_t* gA0 = reinterpret_cast<const int8_t*>(xq) +
                        ((size_t)(m0 + ld_row) * K_DIM) * 2 + ld_col * 16;
    const int8_t* gB0 = reinterpret_cast<const int8_t*>(wb) +
                        ((size_t)(n0 + ld_row) * K_DIM) * 2 + ld_col * 16;
    const size_t GSTEP = (size_t)32 * K_DIM * 2;   // 32 rows in gmem bytes

    // --- ldmatrix base offsets (k-step 0); off[s] = base ^ (s<<5) ---
    const int g  = lane >> 3;
    const int lr = lane & 7;
    int offA[2], offB[4];
#pragma unroll
    for (int f = 0; f < 2; f++) {
        int row = wm * 32 + f * 16 + (g & 1) * 8 + lr;
        int kb  = (g >> 1) * 16;
        offA[f] = row * TILE_ROW_BYTES + (kb ^ ((row & 7) << 4));
    }
#pragma unroll
    for (int j2 = 0; j2 < 4; j2++) {
        int row = wn * 64 + j2 * 16 + (g & 1) * 8 + lr;
        int kb  = (g >> 1) * 16;
        offB[j2] = A_TILE_BYTES + row * TILE_ROW_BYTES + (kb ^ ((row & 7) << 4));
    }

    float acc[2][8][4];                   // [m-frag][n8-frag][4] = 64 regs
#pragma unroll
    for (int f = 0; f < 2; f++)
#pragma unroll
        for (int j = 0; j < 8; j++)
#pragma unroll
            for (int c = 0; c < 4; c++) acc[f][j][c] = 0.0f;

    // --- prologue: issue STAGES-1 stages ---
#pragma unroll
    for (int s = 0; s < STAGES - 1; s++) {
        const uint32_t sb = smem_u + s * STAGE_BYTES;
#pragma unroll
        for (int i = 0; i < 4; i++)
            cp_async16(sb + dstA0 + i * 4096, gA0 + i * GSTEP + s * (BK * 2));
#pragma unroll
        for (int i = 0; i < 4; i++)
            cp_async16(sb + dstB0 + i * 4096, gB0 + i * GSTEP + s * (BK * 2));
        cp_commit();
    }

    // --- mainloop (deferred prefetch) ---
    int cur = 0;
    int nxt = STAGES - 1;
    for (int kt = 0; kt < NK; kt++) {
        cp_wait<STAGES - 2>();
        __syncthreads();

        const uint32_t st = smem_u + cur * STAGE_BYTES;
        const int jt = kt + STAGES - 1;
        const uint32_t sb = smem_u + nxt * STAGE_BYTES;
        const bool do_pf = (jt < NK);

        // ---- kstep 0: feed the tensor pipe FIRST ----
        {
            uint32_t af[2][4], bf[4][4];
#pragma unroll
            for (int f = 0; f < 2; f++)    ldsm_x4(st + offA[f], af[f]);
#pragma unroll
            for (int j2 = 0; j2 < 4; j2++) ldsm_x4(st + offB[j2], bf[j2]);
#pragma unroll
            for (int f = 0; f < 2; f++)
#pragma unroll
                for (int j = 0; j < 8; j++)
                    mma_f16(acc[f][j],
                            af[f][0], af[f][1], af[f][2], af[f][3],
                            bf[j >> 1][(j & 1)], bf[j >> 1][(j & 1) + 2]);
        }

        // ---- prefetch A for tile kt+2 (tensor pipe already busy) ----
        if (do_pf) {
#pragma unroll
            for (int i = 0; i < 4; i++)
                cp_async16(sb + dstA0 + i * 4096, gA0 + i * GSTEP + jt * (BK * 2));
        }

        // ---- kstep 1 ----
        {
            const int sx = 1 << 5;
            uint32_t af[2][4], bf[4][4];
#pragma unroll
            for (int f = 0; f < 2; f++)    ldsm_x4(st + (offA[f] ^ sx), af[f]);
#pragma unroll
            for (int j2 = 0; j2 < 4; j2++) ldsm_x4(st + (offB[j2] ^ sx), bf[j2]);
#pragma unroll
            for (int f = 0; f < 2; f++)
#pragma unroll
                for (int j = 0; j < 8; j++)
                    mma_f16(acc[f][j],
                            af[f][0], af[f][1], af[f][2], af[f][3],
                            bf[j >> 1][(j & 1)], bf[j >> 1][(j & 1) + 2]);
        }

        // ---- prefetch B for tile kt+2, then commit the group ----
        if (do_pf) {
#pragma unroll
            for (int i = 0; i < 4; i++)
                cp_async16(sb + dstB0 + i * 4096, gB0 + i * GSTEP + jt * (BK * 2));
        }
        cp_commit();

        // ---- ksteps 2..3 ----
#pragma unroll
        for (int s = 2; s < 4; s++) {
            const int sx = s << 5;
            uint32_t af[2][4], bf[4][4];
#pragma unroll
            for (int f = 0; f < 2; f++)    ldsm_x4(st + (offA[f] ^ sx), af[f]);
#pragma unroll
            for (int j2 = 0; j2 < 4; j2++) ldsm_x4(st + (offB[j2] ^ sx), bf[j2]);
#pragma unroll
            for (int f = 0; f < 2; f++)
#pragma unroll
                for (int j = 0; j < 8; j++)
                    mma_f16(acc[f][j],
                            af[f][0], af[f][1], af[f][2], af[f][3],
                            bf[j >> 1][(j & 1)], bf[j >> 1][(j & 1) + 2]);
        }

        cur = (cur == STAGES - 1) ? 0 : cur + 1;
        nxt = (nxt == STAGES - 1) ? 0 : nxt + 1;
    }

    // --- epilogue: dequantize + store ---
#pragma unroll
    for (int f = 0; f < 2; f++) {
        int r0 = m0 + wm * 32 + f * 16 + (lane >> 2);
        float al0 = alpha[r0];
        float al1 = alpha[r0 + 8];
        float* o0 = out + (size_t)r0 * N_DIM + n0 + wn * 64 + (lane & 3) * 2;
        float* o1 = o0 + (size_t)8 * N_DIM;
#pragma unroll
        for (int j = 0; j < 8; j++) {
            float2 v0, v1;
            v0.x = acc[f][j][0] * al0;
            v0.y = acc[f][j][1] * al0;
            v1.x = acc[f][j][2] * al1;
            v1.y = acc[f][j][3] * al1;
            *reinterpret_cast<float2*>(o0 + j * 8) = v0;
            *reinterpret_cast<float2*>(o1 + j * 8) = v1;
        }
    }
}

// ============================================================================
// Host side
// ============================================================================
extern "C" void kernel_launch(void* const* d_in, const int* in_sizes, int n_in,
                              void* d_out, int out_size)
{
    const float* x     = (const float*)d_in[0];
    const float* w     = (const float*)d_in[1];
    const float* scale = (const float*)d_in[2];
    float* out = (float*)d_out;

    void *xq_p = nullptr, *wb_p = nullptr, *al_p = nullptr;
    cudaGetSymbolAddress(&xq_p, g_xq);
    cudaGetSymbolAddress(&wb_p, g_wb);
    cudaGetSymbolAddress(&al_p, g_alpha);

    // Phase 1: quantize activations + convert weights
    quant_kernel<<<M_TOK, 128>>>(x, scale, (__half*)xq_p, (float*)al_p);
    wconv_kernel<<<((size_t)N_DIM * K_DIM) / (256 * 4), 256>>>(w, (__half*)wb_p);

    // Phase 2: GEMM (2 CTAs per SM, deferred prefetch)
    cudaFuncSetAttribute(bitlinear_gemm,
                         cudaFuncAttributeMaxDynamicSharedMemorySize, SMEM_TOTAL);
    dim3 grid(N_DIM / BN, M_TOK / BM);   // 32 x 64 = 2048 CTAs
    bitlinear_gemm<<<grid, THREADS, SMEM_TOTAL>>>(
        (const __half*)xq_p, (const __half*)wb_p, (const float*)al_p, out);
}